// round 17
// baseline (speedup 1.0000x reference)
#include <cuda_runtime.h>
#include <cuda_fp16.h>
#include <cstdint>

#define CC 256
#define WW 128
#define HH 64
#define BB 2
#define NCOL (BB*HH)
#define HO 256
#define WO 512
#define NOUT (BB*HO*WO)
#define NROWS 512             // output rows (b,i)
#define NBLK 256              // scan CTAs (32 clusters x 8)
#define CLW 8                 // cluster width

// per-fill transaction bytes: 8 CTAs x 64 threads x 2 x 4B = 4096
#define TXB 4096u

__device__ __half g_M[CC*CC];            // center-tap weights fp16, row-major [o][c]
__device__ float  g_part[WW*NBLK*64];    // per-thread u partials [w][blk][tid64] 8MB
__device__ float  g_u[NCOL*WW];          // reduced (1-channel) pre-upsample result
__device__ float  g_psum[NROWS];
__device__ float  g_psumsq[NROWS];

__device__ __forceinline__ uint32_t smem_u32(const void* p) {
    uint32_t a;
    asm("{ .reg .u64 t; cvta.to.shared.u64 t, %1; cvt.u32.u64 %0, t; }"
        : "=r"(a) : "l"(p));
    return a;
}
__device__ __forceinline__ uint32_t cluster_rank() {
    uint32_t r;
    asm("mov.u32 %0, %%cluster_ctarank;" : "=r"(r));
    return r;
}
__device__ __forceinline__ uint32_t mapa_u32(uint32_t addr, uint32_t rank) {
    uint32_t r;
    asm("mapa.shared::cluster.u32 %0, %1, %2;" : "=r"(r) : "r"(addr), "r"(rank));
    return r;
}
#define ST_ASYNC_U32(addr, val, mbar)                                         \
    asm volatile("st.async.shared::cluster.mbarrier::complete_tx::bytes.u32 " \
                 "[%0], %1, [%2];" :: "r"(addr), "r"(val), "r"(mbar) : "memory")
#define MBAR_INIT(mbar, cnt)                                                  \
    asm volatile("mbarrier.init.shared.b64 [%0], %1;"                         \
                 :: "r"(mbar), "r"((uint32_t)(cnt)) : "memory")
#define MBAR_EXPECT_TX(mbar, bytes)                                           \
    asm volatile("mbarrier.arrive.expect_tx.shared::cta.b64 _, [%0], %1;"     \
                 :: "r"(mbar), "r"((uint32_t)(bytes)) : "memory")
#define MBAR_WAIT(mbar, parity) do {                                          \
    uint32_t _m = (mbar), _p = (parity), _done;                               \
    asm volatile("{ .reg .pred p;\n\t"                                        \
        "mbarrier.try_wait.parity.acquire.cluster.shared::cta.b64 p, [%1], %2;\n\t" \
        "selp.b32 %0, 1, 0, p; }"                                             \
        : "=r"(_done) : "r"(_m), "r"(_p) : "memory");                         \
    if (!_done) {                                                             \
        asm volatile("{ .reg .pred P1;\n\t"                                   \
            "WL_%=:\n\t"                                                      \
            "mbarrier.try_wait.parity.acquire.cluster.shared::cta.b64 P1, [%0], %1, 0x989680;\n\t" \
            "@P1 bra.uni WD_%=;\n\t"                                          \
            "bra.uni WL_%=;\n\t"                                              \
            "WD_%=: }" :: "r"(_m), "r"(_p) : "memory");                       \
    }                                                                         \
} while (0)
#define CLUSTER_SYNC() do {                                                   \
    asm volatile("barrier.cluster.arrive.aligned;" ::: "memory");             \
    asm volatile("barrier.cluster.wait.aligned;"   ::: "memory");             \
} while (0)

// ===========================================================================
__global__ void extract_M_kernel(const float* __restrict__ convw) {
    int i = blockIdx.x * 256 + threadIdx.x;
    g_M[i] = __float2half(convw[i * 9 + 4]);
}

// ===========================================================================
// 8-CTA-cluster HMMA double scan with K-split. 256 CTAs = 32 clusters x
// 4 columns. Each CTA owns 32 channels. Warps 0,1: row-tile t = wid,
// k-chunks 0..7; warps 2,3: same row-tiles, k-chunks 8..15 (partials
// combined via one STS.128 + __syncthreads). Per-SMSP MMA block: 8 x 16 =
// 128 cyc. Per step warps 0,1 fan the new S out to ALL EIGHT CTAs' B
// buffers via st.async (TXB = 4096 per fill).
#define MMA_ASM(dd, a, b0r, b1r)                                              \
    asm volatile(                                                             \
        "mma.sync.aligned.m16n8k16.row.col.f32.f16.f16.f32 "                  \
        "{%0,%1,%2,%3}, {%4,%5,%6,%7}, {%8,%9}, {%0,%1,%2,%3};"               \
        : "+f"((dd)[0]), "+f"((dd)[1]), "+f"((dd)[2]), "+f"((dd)[3])          \
        : "r"((a)[0]), "r"((a)[1]), "r"((a)[2]), "r"((a)[3]),                 \
          "r"(b0r), "r"(b1r))

__global__ void __launch_bounds__(128, 1) __cluster_dims__(CLW, 1, 1)
scnn_hmma_kernel(const float* __restrict__ p2, const float* __restrict__ w1g) {
    __shared__ __align__(128) __half Bbuf[2][CC * 8];   // [buf][k*8 + n] 2x4KB
    __shared__ __align__(16) float4 pbuf[2][32];        // k-half partials
    __shared__ __align__(8) unsigned long long mbar[2];

    const int tid  = threadIdx.x;
    const int wid  = tid >> 5;          // 0..3
    const int lane = tid & 31;
    const int tg   = lane & 3;
    const int g    = lane >> 2;
    const int t    = wid & 1;           // row tile
    const int kh   = wid >> 1;          // k half
    const int col0 = (blockIdx.x >> 3) * 4;
    const int col  = col0 + tg;
    const int b    = col >> 6;
    const int h    = col & 63;
    const uint32_t rank = cluster_rank();   // 0..7

    // ---- A fragments: rows [rank*32 + 16*t, +16), k-chunks [kh*8, +8)
    uint32_t A[8][4];
    const int rlo = (int)rank * 32 + 16 * t + g;
    {
        const uint32_t* Mlo = reinterpret_cast<const uint32_t*>(g_M + rlo * CC);
        const uint32_t* Mhi = reinterpret_cast<const uint32_t*>(g_M + (rlo + 8) * CC);
#pragma unroll
        for (int kl = 0; kl < 8; kl++) {
            int kt = kh * 8 + kl;
            A[kl][0] = Mlo[kt * 8 + tg];
            A[kl][1] = Mhi[kt * 8 + tg];
            A[kl][2] = Mlo[kt * 8 + tg + 4];
            A[kl][3] = Mhi[kt * 8 + tg + 4];
        }
    }

    // channels owned by warps 0,1 threads
    const int ch0 = rlo;
    const int ch1 = rlo + 8;
    const float w1a = w1g[ch0];
    const float w1b = w1g[ch1];

    const float4* xpa = reinterpret_cast<const float4*>(
        p2 + ((size_t)(b * CC + ch0) * HH + h) * WW);
    const float4* xpb = reinterpret_cast<const float4*>(
        p2 + ((size_t)(b * CC + ch1) * HH + h) * WW);

    // u-partial stream (warps 0,1 only): g_part[w][blk][tid64]
    float* gpart = g_part + (size_t)blockIdx.x * 64 + tid;

    // smem addresses: local + all 8 cluster ranks
    const uint32_t b32   = smem_u32(&Bbuf[0][0]);
    const uint32_t bar32 = smem_u32(&mbar[0]);
    uint32_t bAll[CLW], barAll[CLW];
#pragma unroll
    for (int r = 0; r < CLW; r++) {
        bAll[r]   = mapa_u32(b32,   (uint32_t)r);
        barAll[r] = mapa_u32(bar32, (uint32_t)r);
    }
    const uint32_t lmaddr = b32 + (uint32_t)lane * 16u;
    const uint32_t bo0 = (uint32_t)(ch0 * 16 + tg * 4);
    const uint32_t bo1 = (uint32_t)(ch1 * 16 + tg * 4);

    if (tid == 0) { MBAR_INIT(bar32, 1); MBAR_INIT(bar32 + 8, 1); }
    __syncthreads();
    CLUSTER_SYNC();
    if (tid == 0) {
        MBAR_EXPECT_TX(bar32,     TXB);   // fill 0 of buffer 0 (step 0)
        MBAR_EXPECT_TX(bar32 + 8, TXB);   // fill 0 of buffer 1 (step 1)
    }

    // ---- step 0: s1[0] = s2[0] = x[:,0]  -> buffer 0 (all 8 CTAs)
    float4 cura, curb, nxta, nxtb;
    if (wid < 2) {
        cura = xpa[0];
        curb = xpb[0];
        __half2 v0h = __halves2half2(__float2half_rn(cura.x), __float2half_rn(cura.x));
        __half2 v1h = __halves2half2(__float2half_rn(curb.x), __float2half_rn(curb.x));
        uint32_t v0 = *reinterpret_cast<uint32_t*>(&v0h);
        uint32_t v1 = *reinterpret_cast<uint32_t*>(&v1h);
#pragma unroll
        for (int r = 0; r < CLW; r++) {
            ST_ASYNC_U32(bAll[r] + bo0, v0, barAll[r]);
            ST_ASYNC_U32(bAll[r] + bo1, v1, barAll[r]);
        }
        gpart[0] = w1a * cura.x + w1b * curb.x;
    }

    for (int w = 1; w < WW; w++) {
        const int rb = (w - 1) & 1;
        const int wb = rb ^ 1;
        const uint32_t barL = bar32 + (uint32_t)rb * 8u;
        MBAR_WAIT(barL, (uint32_t)(((w - 1) >> 1) & 1));
        if (tid == 0 && w <= 125) MBAR_EXPECT_TX(barL, TXB);   // re-arm

        // B-fragment loads: this warp's 4 k-chunks
        const uint32_t base = lmaddr + (uint32_t)rb * (CC * 8 * 2)
                            + (uint32_t)kh * 2048u;            // kh*4 chunks * 512B
        uint32_t L[4][4];
#pragma unroll
        for (int m8 = 0; m8 < 4; m8++) {
            asm volatile(
                "ldmatrix.sync.aligned.m8n8.x4.trans.shared.b16 "
                "{%0,%1,%2,%3}, [%4];"
                : "=r"(L[m8][0]), "=r"(L[m8][1]), "=r"(L[m8][2]), "=r"(L[m8][3])
                : "r"(base + (uint32_t)m8 * 512u));
        }

        const int j = (w - 1) & 3;
        if (wid < 2 && j == 0 && w + 4 <= WW) {    // prefetch next x group
            nxta = xpa[(w + 3) >> 2];
            nxtb = xpb[(w + 3) >> 2];
        }

        // TWO 4-deep accumulator chains (proven shape, half the count)
        float d[4] = {0.f, 0.f, 0.f, 0.f};
        float e[4] = {0.f, 0.f, 0.f, 0.f};
#pragma unroll
        for (int m8 = 0; m8 < 4; m8++) {
            MMA_ASM(d, A[2 * m8],     L[m8][0], L[m8][1]);
            MMA_ASM(e, A[2 * m8 + 1], L[m8][2], L[m8][3]);
        }

        // k-half 1 publishes partials; k-half 0 combines after the bar
        if (wid >= 2)
            pbuf[t][lane] = make_float4(d[0] + e[0], d[1] + e[1],
                                        d[2] + e[2], d[3] + e[3]);
        __syncthreads();

        if (wid < 2) {
            float4 p = pbuf[t][lane];
            float xa = (j == 0) ? cura.y : (j == 1) ? cura.z : (j == 2) ? cura.w : nxta.x;
            float xb = (j == 0) ? curb.y : (j == 1) ? curb.z : (j == 2) ? curb.w : nxtb.x;

            float s1a = xa + fmaxf((d[0] + e[0]) + p.x, 0.f);
            float s2a = s1a + fmaxf((d[1] + e[1]) + p.y, 0.f);
            float s1b = xb + fmaxf((d[2] + e[2]) + p.z, 0.f);
            float s2b = s1b + fmaxf((d[3] + e[3]) + p.w, 0.f);

            if (w < WW - 1) {
                const uint32_t barOff = (uint32_t)wb * 8u;
                const uint32_t bufOff = (uint32_t)wb * (CC * 8 * 2);
                __half2 v0h = __floats2half2_rn(s1a, s2a);
                __half2 v1h = __floats2half2_rn(s1b, s2b);
                uint32_t v0 = *reinterpret_cast<uint32_t*>(&v0h);
                uint32_t v1 = *reinterpret_cast<uint32_t*>(&v1h);
#pragma unroll
                for (int r = 0; r < CLW; r++) {
                    ST_ASYNC_U32(bAll[r] + bufOff + bo0, v0, barAll[r] + barOff);
                    ST_ASYNC_U32(bAll[r] + bufOff + bo1, v1, barAll[r] + barOff);
                }
            }
            gpart[(size_t)w * (NBLK * 64)] = w1a * s2a + w1b * s2b;

            if (j == 3) { cura = nxta; curb = nxtb; }
        }
    }

    CLUSTER_SYNC();
}

// ===========================================================================
// Reduce u: g_u[col][127-w] = sum over (rank, warp01, g) of g_part.
// grid = 128 (w), block = 128 (col). Deterministic fixed-order summation.
// Column c: cg = c>>2, tg = c&3; blocks cg*8+rank; tids (q>>3)*32+(q&7)*4+tg.
__global__ void reduce_u_kernel() {
    int w = blockIdx.x;
    int c = threadIdx.x;              // column 0..127
    int tg = c & 3;
    int cg = c >> 2;                  // cluster 0..31
    const float* base = g_part + (size_t)w * (NBLK * 64);
    float s = 0.f;
#pragma unroll
    for (int rank = 0; rank < 8; rank++) {
        const float* pb = base + (cg * 8 + rank) * 64;
#pragma unroll
        for (int q = 0; q < 16; q++)
            s += pb[(q >> 3) * 32 + (q & 7) * 4 + tg];
    }
    g_u[c * WW + (WW - 1 - w)] = s;
}

// ===========================================================================
__device__ __forceinline__ void stage_rows(float* su0, float* su1,
                                           int b, int i, float& wy) {
    float ys = (float)i * (63.0f / 255.0f);
    int y0 = (int)ys;
    wy = ys - (float)y0;
    int y1 = min(y0 + 1, HH - 1);
    int t = threadIdx.x;
    if (t < 128)      su0[t]       = g_u[(b * HH + y0) * WW + t];
    else if (t < 256) su1[t - 128] = g_u[(b * HH + y1) * WW + (t - 128)];
}

__device__ __forceinline__ float bilin(const float* su0, const float* su1,
                                       int j, float wy) {
    float xs = (float)j * (127.0f / 511.0f);
    int x0 = (int)xs;
    float wx = xs - (float)x0;
    int x1 = min(x0 + 1, WW - 1);
    float r0 = su0[x0] * (1.f - wy) + su1[x0] * wy;
    float r1 = su0[x1] * (1.f - wy) + su1[x1] * wy;
    return r0 * (1.f - wx) + r1 * wx;
}

__global__ void stats_kernel() {
    __shared__ float su0[128], su1[128];
    __shared__ float rs[8], rq[8];
    int row = blockIdx.x;
    int b = row >> 8, i = row & 255;
    float wy;
    stage_rows(su0, su1, b, i, wy);
    __syncthreads();

    int t = threadIdx.x;
    float sum = 0.f, sq = 0.f;
#pragma unroll
    for (int rr = 0; rr < 2; rr++) {
        float v = bilin(su0, su1, t + rr * 256, wy);
        sum += v;
        sq  += v * v;
    }
#pragma unroll
    for (int o = 16; o; o >>= 1) {
        sum += __shfl_xor_sync(0xffffffffu, sum, o);
        sq  += __shfl_xor_sync(0xffffffffu, sq,  o);
    }
    if ((t & 31) == 0) { rs[t >> 5] = sum; rq[t >> 5] = sq; }
    __syncthreads();
    if (t == 0) {
        float a = 0.f, c = 0.f;
#pragma unroll
        for (int k = 0; k < 8; k++) { a += rs[k]; c += rq[k]; }
        g_psum[row] = a; g_psumsq[row] = c;
    }
}

// output kernel with finalize folded in.
__global__ void output_kernel(float* __restrict__ out,
                              const float* __restrict__ gamma,
                              const float* __restrict__ beta) {
    __shared__ float su0[128], su1[128];
    __shared__ float rs[8], rq[8];
    __shared__ float stats2[2];
    int row = blockIdx.x;
    int b = row >> 8, i = row & 255;
    float wy;
    stage_rows(su0, su1, b, i, wy);

    int t = threadIdx.x;
    float sum = g_psum[t] + g_psum[t + 256];
    float sq  = g_psumsq[t] + g_psumsq[t + 256];
#pragma unroll
    for (int o = 16; o; o >>= 1) {
        sum += __shfl_xor_sync(0xffffffffu, sum, o);
        sq  += __shfl_xor_sync(0xffffffffu, sq,  o);
    }
    if ((t & 31) == 0) { rs[t >> 5] = sum; rq[t >> 5] = sq; }
    __syncthreads();
    if (t == 0) {
        float a = 0.f, c = 0.f;
#pragma unroll
        for (int k = 0; k < 8; k++) { a += rs[k]; c += rq[k]; }
        float inv_n = 1.0f / (float)NOUT;
        float mean  = a * inv_n;
        float var   = c * inv_n - mean * mean;
        stats2[0] = mean;
        stats2[1] = rsqrtf(var + 1e-5f);
    }
    __syncthreads();

    float mean = stats2[0], istd = stats2[1];
    float gm = gamma[0], bt = beta[0];
#pragma unroll
    for (int rr = 0; rr < 2; rr++) {
        int j = t + rr * 256;
        float v = bilin(su0, su1, j, wy);
        float y = (v - mean) * istd * gm + bt;
        out[row * WO + j] = 1.0f / (1.0f + expf(-y));
    }
}

// ===========================================================================
extern "C" void kernel_launch(void* const* d_in, const int* in_sizes, int n_in,
                              void* d_out, int out_size) {
    const float* p2    = (const float*)d_in[0];
    const float* convw = (const float*)d_in[1];
    const float* conv1 = (const float*)d_in[2];
    const float* gamma = (const float*)d_in[3];
    const float* beta  = (const float*)d_in[4];
    float* out = (float*)d_out;

    extract_M_kernel<<<256, 256>>>(convw);
    scnn_hmma_kernel<<<NBLK, 128>>>(p2, conv1);
    reduce_u_kernel<<<WW, 128>>>();
    stats_kernel<<<NROWS, 256>>>();
    output_kernel<<<NROWS, 256>>>(out, gamma, beta);
}